// round 2
// baseline (speedup 1.0000x reference)
#include <cuda_runtime.h>

#define NB   2
#define CCH  128
#define HH   64
#define WWD  64
#define HW   (HH*WWD)
#define NPIX (NB*HW)

#define T1PX 32     // pixels per block, kernel 1
#define TILE 32     // pixels per block, kernel 2
#define HCOL 40     // halo cols = TILE + 8
#define LWIN 9
#define KK   81

// scratch: pixel-major transposed tensors [p][c]
__device__ float g_kt[NPIX*CCH];   // key  = W @ ft
__device__ float g_qt[NPIX*CCH];   // query= W @ fk
__device__ float g_ftt[NPIX*CCH];  // ft transposed

typedef unsigned long long ull;

__device__ __forceinline__ ull pack2(float x, float y) {
    ull r;
    asm("mov.b64 %0, {%1, %2};" : "=l"(r) : "f"(x), "f"(y));
    return r;
}
__device__ __forceinline__ ull fma2(ull a, ull b, ull c) {
    ull d;
    asm("fma.rn.f32x2 %0, %1, %2, %3;" : "=l"(d) : "l"(a), "l"(b), "l"(c));
    return d;
}
__device__ __forceinline__ float2 unpack2(ull p) {
    float x, y;
    asm("mov.b64 {%0, %1}, %2;" : "=f"(x), "=f"(y) : "l"(p));
    return make_float2(x, y);
}

// ---------------------------------------------------------------------------
// Kernel 1: key = W@ft, query = W@fk (1x1 conv == channel GEMM), plus
// transpose of ft. Outputs pixel-major [p][c] for contiguous vector loads.
// 128 threads, 32 pixels/block. Register tile: 8 o x 4 px per thread,
// packed f32x2 FMAs.
// ---------------------------------------------------------------------------
__global__ void __launch_bounds__(128) proj_kernel(
    const float* __restrict__ ft, const float* __restrict__ fk,
    const float* __restrict__ Wm)
{
    extern __shared__ float sm[];
    float* sW = sm;                  // 128*128
    float* sA = sW + CCH*CCH;        // 128*36 (ft tile, padded)
    float* sB = sA + CCH*36;         // 128*36 (fk tile, padded)
    float* sS = sB + CCH*36;         // 32*129 staging

    const int t  = threadIdx.x;
    const int p0 = blockIdx.x * T1PX;
    const int n  = p0 / HW;
    const int pp = p0 - n * HW;
    const float* fta = ft + n*CCH*HW + pp;
    const float* fka = fk + n*CCH*HW + pp;

    for (int j = t; j < CCH*CCH; j += 128) sW[j] = Wm[j];
    for (int j = t; j < CCH*T1PX; j += 128) {
        int i = j >> 5, px = j & 31;
        sA[i*36 + px] = fta[i*HW + px];
        sB[i*36 + px] = fka[i*HW + px];
    }
    __syncthreads();

    const int px4 = (t & 7) * 4;     // 8 groups of 4 consecutive px
    const int o0  = (t >> 3) * 8;    // 16 groups of 8 output channels

    ull aK[8][2], aQ[8][2];
#pragma unroll
    for (int oo = 0; oo < 8; oo++) {
        aK[oo][0] = aK[oo][1] = 0ull;
        aQ[oo][0] = aQ[oo][1] = 0ull;
    }

#pragma unroll 4
    for (int i = 0; i < CCH; i++) {
        float4 a = *(const float4*)&sA[i*36 + px4];
        float4 b = *(const float4*)&sB[i*36 + px4];
        ull a01 = pack2(a.x, a.y), a23 = pack2(a.z, a.w);
        ull b01 = pack2(b.x, b.y), b23 = pack2(b.z, b.w);
#pragma unroll
        for (int oo = 0; oo < 8; oo++) {
            float w = sW[(o0+oo)*CCH + i];
            ull ww = pack2(w, w);
            aK[oo][0] = fma2(a01, ww, aK[oo][0]);
            aK[oo][1] = fma2(a23, ww, aK[oo][1]);
            aQ[oo][0] = fma2(b01, ww, aQ[oo][0]);
            aQ[oo][1] = fma2(b23, ww, aQ[oo][1]);
        }
    }

    // stage + coalesced write: key
#pragma unroll
    for (int oo = 0; oo < 8; oo++) {
        float2 v0 = unpack2(aK[oo][0]);
        float2 v1 = unpack2(aK[oo][1]);
        sS[(px4+0)*129 + o0+oo] = v0.x;
        sS[(px4+1)*129 + o0+oo] = v0.y;
        sS[(px4+2)*129 + o0+oo] = v1.x;
        sS[(px4+3)*129 + o0+oo] = v1.y;
    }
    __syncthreads();
    float* gk = g_kt + p0*CCH;
    for (int j = t; j < T1PX*CCH; j += 128)
        gk[j] = sS[(j>>7)*129 + (j & 127)];
    __syncthreads();

    // stage + coalesced write: query
#pragma unroll
    for (int oo = 0; oo < 8; oo++) {
        float2 v0 = unpack2(aQ[oo][0]);
        float2 v1 = unpack2(aQ[oo][1]);
        sS[(px4+0)*129 + o0+oo] = v0.x;
        sS[(px4+1)*129 + o0+oo] = v0.y;
        sS[(px4+2)*129 + o0+oo] = v1.x;
        sS[(px4+3)*129 + o0+oo] = v1.y;
    }
    __syncthreads();
    float* gq = g_qt + p0*CCH;
    for (int j = t; j < T1PX*CCH; j += 128)
        gq[j] = sS[(j>>7)*129 + (j & 127)];

    // ft transpose (reads sA, conflict-light due to pad 36)
    float* gf = g_ftt + p0*CCH;
    for (int j = t; j < T1PX*CCH; j += 128) {
        int px = j >> 7, c = j & 127;
        gf[j] = sA[c*36 + px];
    }
}

// ---------------------------------------------------------------------------
// Kernel 2: per-pixel local attention.
//   Phase A: sim[px][di*9+dj] = q[px] . key[y+di-4][x+dj-4]  (SMEM halo,
//            register reuse: each key vector FMA'd vs up to 4 px)
//   Phase B: softmax over 81 (warp-parallel)
//   Phase C: out[c][px] = sum_k weight * ft_halo  (same reuse pattern)
//   Output staged through SMEM for coalesced (n,c,h,w) stores.
// 256 threads (8 warps x 4 px), grid (2, 64, 2).
// ---------------------------------------------------------------------------
__device__ __forceinline__ void load_halo(const float* __restrict__ src,
                                          float* halo, int n, int y, int x0,
                                          int w, int lane)
{
    const int c4 = lane * 4;
#pragma unroll 1
    for (int v = w*45; v < w*45 + 45; v++) {   // 9*40 = 360 vectors / 8 warps
        int row = v / HCOL;
        int col = v - row*HCOL;
        int gy = y + row - 4;
        int gx = x0 + col - 4;
        float4 val = make_float4(0.f, 0.f, 0.f, 0.f);
        if ((unsigned)gy < (unsigned)HH && (unsigned)gx < (unsigned)WWD)
            val = *(const float4*)&src[((n*HH + gy)*WWD + gx)*CCH + c4];
        *(float4*)&halo[v*CCH + c4] = val;
    }
}

__global__ void __launch_bounds__(256) attn_kernel(float* __restrict__ out)
{
    extern __shared__ float sm[];
    float* halo = sm;                   // [9][40][128] = 46080 floats
    float* simw = sm + LWIN*HCOL*CCH;   // [32][81]

    const int t = threadIdx.x, lane = t & 31, w = t >> 5;
    const int x0 = blockIdx.x * TILE;
    const int y  = blockIdx.y;
    const int n  = blockIdx.z;
    const int pb = w * 4;               // this warp's 4 consecutive px
    const int c4 = lane * 4;

    // load query vectors for this warp's pixels (packed f32x2 pairs)
    ull q01[4], q23[4];
#pragma unroll
    for (int u = 0; u < 4; u++) {
        float4 q = *(const float4*)&g_qt[((n*HH + y)*WWD + x0 + pb + u)*CCH + c4];
        q01[u] = pack2(q.x, q.y);
        q23[u] = pack2(q.z, q.w);
    }

    load_halo(g_kt, halo, n, y, x0, w, lane);
    __syncthreads();

    // ---- Phase A: similarities ----
#pragma unroll 1
    for (int di = 0; di < LWIN; di++) {
        ull acc[4][9];
#pragma unroll
        for (int u = 0; u < 4; u++)
#pragma unroll
            for (int dj = 0; dj < 9; dj++) acc[u][dj] = 0ull;

#pragma unroll
        for (int jj = 0; jj < 12; jj++) {
            float4 k4 = *(const float4*)&halo[(di*HCOL + pb + jj)*CCH + c4];
            ull k01 = pack2(k4.x, k4.y), k23 = pack2(k4.z, k4.w);
#pragma unroll
            for (int u = 0; u < 4; u++) {
                int dj = jj - u;
                if (dj >= 0 && dj < 9) {
                    acc[u][dj] = fma2(q01[u], k01, acc[u][dj]);
                    acc[u][dj] = fma2(q23[u], k23, acc[u][dj]);
                }
            }
        }
#pragma unroll
        for (int u = 0; u < 4; u++) {
#pragma unroll
            for (int dj = 0; dj < 9; dj++) {
                float2 p = unpack2(acc[u][dj]);
                float v = p.x + p.y;
                v += __shfl_xor_sync(0xffffffffu, v, 16);
                v += __shfl_xor_sync(0xffffffffu, v, 8);
                v += __shfl_xor_sync(0xffffffffu, v, 4);
                v += __shfl_xor_sync(0xffffffffu, v, 2);
                v += __shfl_xor_sync(0xffffffffu, v, 1);
                if (lane == 0) simw[(pb+u)*KK + di*LWIN + dj] = v;
            }
        }
    }
    __syncthreads();

    // ---- Phase B: softmax over 81 (warp handles its 4 px; 81 = 32+32+17) ----
#pragma unroll 1
    for (int u = 0; u < 4; u++) {
        float* srow = simw + (pb+u)*KK;
        float v0 = srow[lane];
        float v1 = srow[32 + lane];
        float v2 = (lane < 17) ? srow[64 + lane] : -1e30f;
        float m = fmaxf(fmaxf(v0, v1), v2);
        m = fmaxf(m, __shfl_xor_sync(0xffffffffu, m, 16));
        m = fmaxf(m, __shfl_xor_sync(0xffffffffu, m, 8));
        m = fmaxf(m, __shfl_xor_sync(0xffffffffu, m, 4));
        m = fmaxf(m, __shfl_xor_sync(0xffffffffu, m, 2));
        m = fmaxf(m, __shfl_xor_sync(0xffffffffu, m, 1));
        float e0 = __expf(v0 - m);
        float e1 = __expf(v1 - m);
        float e2 = (lane < 17) ? __expf(v2 - m) : 0.f;
        float s = e0 + e1 + e2;
        s += __shfl_xor_sync(0xffffffffu, s, 16);
        s += __shfl_xor_sync(0xffffffffu, s, 8);
        s += __shfl_xor_sync(0xffffffffu, s, 4);
        s += __shfl_xor_sync(0xffffffffu, s, 2);
        s += __shfl_xor_sync(0xffffffffu, s, 1);
        float inv = 1.0f / s;
        srow[lane]      = e0 * inv;
        srow[32 + lane] = e1 * inv;
        if (lane < 17) srow[64 + lane] = e2 * inv;
    }

    // reload halo with raw ft (phase A done; simw untouched by loader)
    load_halo(g_ftt, halo, n, y, x0, w, lane);
    __syncthreads();

    // ---- Phase C: weighted aggregation ----
    ull o01[4], o23[4];
#pragma unroll
    for (int u = 0; u < 4; u++) { o01[u] = 0ull; o23[u] = 0ull; }

#pragma unroll 1
    for (int di = 0; di < LWIN; di++) {
#pragma unroll
        for (int jj = 0; jj < 12; jj++) {
            float4 f4 = *(const float4*)&halo[(di*HCOL + pb + jj)*CCH + c4];
            ull f01 = pack2(f4.x, f4.y), f23 = pack2(f4.z, f4.w);
#pragma unroll
            for (int u = 0; u < 4; u++) {
                int dj = jj - u;
                if (dj >= 0 && dj < 9) {
                    float wv = simw[(pb+u)*KK + di*LWIN + dj];  // broadcast
                    ull ww = pack2(wv, wv);
                    o01[u] = fma2(f01, ww, o01[u]);
                    o23[u] = fma2(f23, ww, o23[u]);
                }
            }
        }
    }
    __syncthreads();   // done reading halo; reuse it as output staging

    float* sout = sm;  // [32][132] padded, float4-aligned rows
#pragma unroll
    for (int u = 0; u < 4; u++) {
        float2 a = unpack2(o01[u]);
        float2 b = unpack2(o23[u]);
        *(float4*)&sout[(pb+u)*132 + c4] = make_float4(a.x, a.y, b.x, b.y);
    }
    __syncthreads();

    // coalesced (n,c,h,w) store
    float* ob = out + (n*CCH*HH + y)*WWD + x0;
    for (int j = t; j < CCH*TILE; j += 256) {
        int c = j >> 5, px = j & 31;
        ob[c*HW + px] = sout[px*132 + c];
    }
}

// ---------------------------------------------------------------------------
extern "C" void kernel_launch(void* const* d_in, const int* in_sizes, int n_in,
                              void* d_out, int out_size)
{
    (void)in_sizes; (void)n_in; (void)out_size;
    const float* ft = (const float*)d_in[0];
    const float* fk = (const float*)d_in[1];
    const float* Wm = (const float*)d_in[2];
    float* out = (float*)d_out;

    const size_t smem1 = (CCH*CCH + 2*CCH*36 + 32*129) * sizeof(float);   // ~116 KB
    const size_t smem2 = (LWIN*HCOL*CCH + 32*KK) * sizeof(float);         // ~190 KB

    cudaFuncSetAttribute(proj_kernel, cudaFuncAttributeMaxDynamicSharedMemorySize,
                         (int)smem1);
    cudaFuncSetAttribute(attn_kernel, cudaFuncAttributeMaxDynamicSharedMemorySize,
                         (int)smem2);

    proj_kernel<<<NPIX / T1PX, 128, smem1>>>(ft, fk, Wm);

    dim3 g2(WWD / TILE, HH, NB);
    attn_kernel<<<g2, 256, smem2>>>(out);
}

// round 4
// speedup vs baseline: 2.1015x; 2.1015x over previous
#include <cuda_runtime.h>

#define NB   2
#define CCH  128
#define HH   64
#define WWD  64
#define HW   (HH*WWD)
#define NPIX (NB*HW)

#define T1PX 16     // pixels per block, kernel 1
#define TILE 32     // pixels per block, kernel 2
#define HCOL 40     // halo cols = TILE + 8
#define LWIN 9
#define KK   81
#define PMLD 33     // pmat row stride (33 % 32 == 1 -> conflict-free)

// scratch: pixel-major transposed tensors [p][c]
__device__ float g_kt[NPIX*CCH];
__device__ float g_qt[NPIX*CCH];
__device__ float g_ftt[NPIX*CCH];

typedef unsigned long long ull;

__device__ __forceinline__ ull pack2(float x, float y) {
    ull r;
    asm("mov.b64 %0, {%1, %2};" : "=l"(r) : "f"(x), "f"(y));
    return r;
}
__device__ __forceinline__ ull fma2(ull a, ull b, ull c) {
    ull d;
    asm("fma.rn.f32x2 %0, %1, %2, %3;" : "=l"(d) : "l"(a), "l"(b), "l"(c));
    return d;
}
__device__ __forceinline__ float2 unpack2(ull p) {
    float x, y;
    asm("mov.b64 {%0, %1}, %2;" : "=f"(x), "=f"(y) : "l"(p));
    return make_float2(x, y);
}

// ---------------------------------------------------------------------------
// Kernel 1: key = W@ft, query = W@fk. 128 threads, 16 px/block, 512 blocks.
// Thread tile: 4 o x 4 px x {K,Q} = 16 f32x2 accumulators (32 regs, no spill).
// W read via LDG.128 (L1-resident, broadcast across the 4 px-groups).
// Outputs pixel-major [p][c] + transposed ft.
// ---------------------------------------------------------------------------
__global__ void __launch_bounds__(128) proj_kernel(
    const float* __restrict__ ft, const float* __restrict__ fk,
    const float* __restrict__ Wm)
{
    extern __shared__ float sm[];
    float* sA = sm;                  // [128][20]
    float* sB = sA + CCH*20;         // [128][20]
    float* sS = sB + CCH*20;         // [16][129] staging

    const int t  = threadIdx.x;
    const int p0 = blockIdx.x * T1PX;
    const int n  = p0 / HW;
    const int pp = p0 - n * HW;
    const float* fta = ft + n*CCH*HW + pp;
    const float* fka = fk + n*CCH*HW + pp;

    for (int j = t; j < CCH*T1PX; j += 128) {
        int i = j >> 4, px = j & 15;
        sA[i*20 + px] = fta[i*HW + px];
        sB[i*20 + px] = fka[i*HW + px];
    }
    __syncthreads();

    const int px4 = (t & 3) * 4;     // 4 groups of 4 px
    const int o0  = (t >> 2) * 4;    // 32 groups of 4 output channels

    ull aK[4][2], aQ[4][2];
#pragma unroll
    for (int oo = 0; oo < 4; oo++) {
        aK[oo][0] = aK[oo][1] = 0ull;
        aQ[oo][0] = aQ[oo][1] = 0ull;
    }

    for (int i = 0; i < CCH; i += 4) {
        float4 w4[4];
#pragma unroll
        for (int oo = 0; oo < 4; oo++)
            w4[oo] = *(const float4*)&Wm[(o0+oo)*CCH + i];
#pragma unroll
        for (int ii = 0; ii < 4; ii++) {
            float4 a = *(const float4*)&sA[(i+ii)*20 + px4];
            float4 b = *(const float4*)&sB[(i+ii)*20 + px4];
            ull a01 = pack2(a.x, a.y), a23 = pack2(a.z, a.w);
            ull b01 = pack2(b.x, b.y), b23 = pack2(b.z, b.w);
#pragma unroll
            for (int oo = 0; oo < 4; oo++) {
                float w = (ii == 0) ? w4[oo].x : (ii == 1) ? w4[oo].y
                        : (ii == 2) ? w4[oo].z : w4[oo].w;
                ull ww = pack2(w, w);
                aK[oo][0] = fma2(a01, ww, aK[oo][0]);
                aK[oo][1] = fma2(a23, ww, aK[oo][1]);
                aQ[oo][0] = fma2(b01, ww, aQ[oo][0]);
                aQ[oo][1] = fma2(b23, ww, aQ[oo][1]);
            }
        }
    }

    // stage + coalesced write: key
#pragma unroll
    for (int oo = 0; oo < 4; oo++) {
        float2 v0 = unpack2(aK[oo][0]);
        float2 v1 = unpack2(aK[oo][1]);
        sS[(px4+0)*129 + o0+oo] = v0.x;
        sS[(px4+1)*129 + o0+oo] = v0.y;
        sS[(px4+2)*129 + o0+oo] = v1.x;
        sS[(px4+3)*129 + o0+oo] = v1.y;
    }
    __syncthreads();
    float* gk = g_kt + p0*CCH;
    for (int j = t; j < T1PX*CCH; j += 128)
        gk[j] = sS[(j>>7)*129 + (j & 127)];
    __syncthreads();

    // stage + coalesced write: query
#pragma unroll
    for (int oo = 0; oo < 4; oo++) {
        float2 v0 = unpack2(aQ[oo][0]);
        float2 v1 = unpack2(aQ[oo][1]);
        sS[(px4+0)*129 + o0+oo] = v0.x;
        sS[(px4+1)*129 + o0+oo] = v0.y;
        sS[(px4+2)*129 + o0+oo] = v1.x;
        sS[(px4+3)*129 + o0+oo] = v1.y;
    }
    __syncthreads();
    float* gq = g_qt + p0*CCH;
    for (int j = t; j < T1PX*CCH; j += 128)
        gq[j] = sS[(j>>7)*129 + (j & 127)];

    // ft transpose
    float* gf = g_ftt + p0*CCH;
    for (int j = t; j < T1PX*CCH; j += 128) {
        int px = j >> 7, c = j & 127;
        gf[j] = sA[c*20 + px];
    }
}

// ---------------------------------------------------------------------------
// Kernel 2: local attention, rolling one-row halo + smem transpose reduce.
// 256 threads (8 warps x 4 px), grid (2, 64, 2), ~67 KB smem -> 3 blocks/SM.
// ---------------------------------------------------------------------------
__device__ __forceinline__ void loadrow(const float* __restrict__ src,
                                        float4* pf, int n, int gy, int x0,
                                        int w, int c4)
{
#pragma unroll
    for (int k = 0; k < 5; k++) {
        int s  = w*5 + k;
        int gx = x0 + s - 4;
        float4 v = make_float4(0.f, 0.f, 0.f, 0.f);
        if ((unsigned)gy < (unsigned)HH && (unsigned)gx < (unsigned)WWD)
            v = *(const float4*)&src[((n*HH + gy)*WWD + gx)*CCH + c4];
        pf[k] = v;
    }
}
__device__ __forceinline__ void stsrow(float* buf, const float4* pf,
                                       int w, int c4)
{
#pragma unroll
    for (int k = 0; k < 5; k++)
        *(float4*)&buf[(w*5 + k)*CCH + c4] = pf[k];
}

__global__ void __launch_bounds__(256) attn_kernel(float* __restrict__ out)
{
    extern __shared__ float sm[];
    float* buf  = sm;                    // [40][128] = 5120 fl
    float* simw = buf + HCOL*CCH;        // [32][81]  = 2592 fl
    float* pmat = simw + TILE*KK;        // 8 * [36][33] = 9504 fl

    const int t = threadIdx.x, lane = t & 31, w = t >> 5;
    const int x0 = blockIdx.x * TILE;
    const int y  = blockIdx.y;
    const int n  = blockIdx.z;
    const int pb = w * 4;
    const int c4 = lane * 4;

    float* pmw = pmat + w * 36*PMLD;
    // reduce-output mapping: lane -> value v = lane (v = u*9+dj)
    const int vu  = lane / 9;
    const int vdj = lane - vu*9;
    float* simw_main = simw + (pb + vu)*KK + vdj;        // + di*9
    float* simw_tail = simw + (pb + 3)*KK + 5 + lane;    // rows 32..35 (lane<4)

    // query vectors (packed)
    ull q01[4], q23[4];
#pragma unroll
    for (int u = 0; u < 4; u++) {
        float4 q = *(const float4*)&g_qt[((n*HH + y)*WWD + x0 + pb + u)*CCH + c4];
        q01[u] = pack2(q.x, q.y);
        q23[u] = pack2(q.z, q.w);
    }

    float4 pf[5];

    // ================= Phase A: similarities =================
    loadrow(g_kt, pf, n, y - 4, x0, w, c4);
    stsrow(buf, pf, w, c4);
    __syncthreads();

#pragma unroll 1
    for (int di = 0; di < LWIN; di++) {
        if (di < LWIN-1) loadrow(g_kt, pf, n, y + di + 1 - 4, x0, w, c4);

        // streamed partials: each (u,dj) done after its single jj
#pragma unroll
        for (int jj = 0; jj < 12; jj++) {
            float4 k4 = *(const float4*)&buf[(pb + jj)*CCH + c4];
            ull k01 = pack2(k4.x, k4.y), k23 = pack2(k4.z, k4.w);
#pragma unroll
            for (int u = 0; u < 4; u++) {
                int dj = jj - u;
                if (dj >= 0 && dj < 9) {
                    ull tt = fma2(q01[u], k01, 0ull);
                    tt = fma2(q23[u], k23, tt);
                    float2 p = unpack2(tt);
                    pmw[(u*9 + dj)*PMLD + lane] = p.x + p.y;
                }
            }
        }
        __syncwarp();
        // transpose reduce: lane sums row 'lane' (conflict-free, 33%32==1)
        {
            const float* r = pmw + lane*PMLD;
            float s0 = 0.f, s1 = 0.f, s2 = 0.f, s3 = 0.f;
#pragma unroll
            for (int j = 0; j < 8; j++) {
                s0 += r[j]; s1 += r[8+j]; s2 += r[16+j]; s3 += r[24+j];
            }
            simw_main[di*LWIN] = (s0 + s1) + (s2 + s3);
            if (lane < 4) {
                const float* r2 = pmw + (32 + lane)*PMLD;
                float t0 = 0.f, t1 = 0.f, t2 = 0.f, t3 = 0.f;
#pragma unroll
                for (int j = 0; j < 8; j++) {
                    t0 += r2[j]; t1 += r2[8+j]; t2 += r2[16+j]; t3 += r2[24+j];
                }
                simw_tail[di*LWIN] = (t0 + t1) + (t2 + t3);
            }
        }
        __syncwarp();

        __syncthreads();                 // all warps done reading buf row di
        if (di < LWIN-1) stsrow(buf, pf, w, c4);
        __syncthreads();                 // buf ready (also orders simw for B)
    }

    // ================= Phase B: softmax over 81 (warp-local rows) ==========
#pragma unroll 1
    for (int u = 0; u < 4; u++) {
        float* srow = simw + (pb + u)*KK;
        float v0 = srow[lane];
        float v1 = srow[32 + lane];
        float v2 = (lane < 17) ? srow[64 + lane] : -1e30f;
        float m = fmaxf(fmaxf(v0, v1), v2);
        m = fmaxf(m, __shfl_xor_sync(0xffffffffu, m, 16));
        m = fmaxf(m, __shfl_xor_sync(0xffffffffu, m, 8));
        m = fmaxf(m, __shfl_xor_sync(0xffffffffu, m, 4));
        m = fmaxf(m, __shfl_xor_sync(0xffffffffu, m, 2));
        m = fmaxf(m, __shfl_xor_sync(0xffffffffu, m, 1));
        float e0 = __expf(v0 - m);
        float e1 = __expf(v1 - m);
        float e2 = (lane < 17) ? __expf(v2 - m) : 0.f;
        float s = e0 + e1 + e2;
        s += __shfl_xor_sync(0xffffffffu, s, 16);
        s += __shfl_xor_sync(0xffffffffu, s, 8);
        s += __shfl_xor_sync(0xffffffffu, s, 4);
        s += __shfl_xor_sync(0xffffffffu, s, 2);
        s += __shfl_xor_sync(0xffffffffu, s, 1);
        float inv = 1.0f / s;
        srow[lane]      = e0 * inv;
        srow[32 + lane] = e1 * inv;
        if (lane < 17) srow[64 + lane] = e2 * inv;
    }
    __syncwarp();

    // ================= Phase C: weighted aggregation =================
    ull o01[4], o23[4];
#pragma unroll
    for (int u = 0; u < 4; u++) { o01[u] = 0ull; o23[u] = 0ull; }

    loadrow(g_ftt, pf, n, y - 4, x0, w, c4);
    __syncthreads();                     // all warps done with buf / simw(A)
    stsrow(buf, pf, w, c4);
    __syncthreads();

#pragma unroll 1
    for (int di = 0; di < LWIN; di++) {
        if (di < LWIN-1) loadrow(g_ftt, pf, n, y + di + 1 - 4, x0, w, c4);

#pragma unroll
        for (int jj = 0; jj < 12; jj++) {
            float4 f4 = *(const float4*)&buf[(pb + jj)*CCH + c4];
            ull f01 = pack2(f4.x, f4.y), f23 = pack2(f4.z, f4.w);
#pragma unroll
            for (int u = 0; u < 4; u++) {
                int dj = jj - u;
                if (dj >= 0 && dj < 9) {
                    float wv = simw[(pb + u)*KK + di*LWIN + dj];
                    ull ww = pack2(wv, wv);
                    o01[u] = fma2(f01, ww, o01[u]);
                    o23[u] = fma2(f23, ww, o23[u]);
                }
            }
        }
        __syncthreads();
        if (di < LWIN-1) stsrow(buf, pf, w, c4);
        __syncthreads();
    }

    // output staging (reuse buf) + coalesced (n,c,h,w) store
    float* sout = buf;                   // [32][132]
#pragma unroll
    for (int u = 0; u < 4; u++) {
        float2 a = unpack2(o01[u]);
        float2 b = unpack2(o23[u]);
        *(float4*)&sout[(pb+u)*132 + c4] = make_float4(a.x, a.y, b.x, b.y);
    }
    __syncthreads();

    float* ob = out + (n*CCH*HH + y)*WWD + x0;
    for (int j = t; j < CCH*TILE; j += 256) {
        int c = j >> 5, px = j & 31;
        ob[c*HW + px] = sout[px*132 + c];
    }
}

// ---------------------------------------------------------------------------
extern "C" void kernel_launch(void* const* d_in, const int* in_sizes, int n_in,
                              void* d_out, int out_size)
{
    (void)in_sizes; (void)n_in; (void)out_size;
    const float* ft = (const float*)d_in[0];
    const float* fk = (const float*)d_in[1];
    const float* Wm = (const float*)d_in[2];
    float* out = (float*)d_out;

    const size_t smem1 = (2*CCH*20 + T1PX*129) * sizeof(float);            // ~28.7 KB
    const size_t smem2 = (HCOL*CCH + TILE*KK + 8*36*PMLD) * sizeof(float); // ~67.3 KB

    cudaFuncSetAttribute(proj_kernel, cudaFuncAttributeMaxDynamicSharedMemorySize,
                         (int)smem1);
    cudaFuncSetAttribute(attn_kernel, cudaFuncAttributeMaxDynamicSharedMemorySize,
                         (int)smem2);

    proj_kernel<<<NPIX / T1PX, 128, smem1>>>(ft, fk, Wm);

    dim3 g2(WWD / TILE, HH, NB);
    attn_kernel<<<g2, 256, smem2>>>(out);
}